// round 13
// baseline (speedup 1.0000x reference)
#include <cuda_runtime.h>
#include <cuda_bf16.h>
#include <cstdint>

#define CIN   128
#define COUT  128
#define KHW   9
#define NB    (CIN*COUT*KHW)   // 147456
#define ZD    256
#define BATCH 32
#define HW    32
#define HW2   (HW*HW)

// ---------------- scratch (device globals; no allocs allowed) ----------------
__device__ __align__(1024) float g_W2[BATCH * 9 * 128 * 128];      // tf32-rounded (b, uv, s, f)
__device__ __align__(1024) float g_xt[BATCH * 34 * 36 * 128];      // tf32-rounded (b,row,col,s); pad stays 0

// ---------------- helpers ----------------
__device__ __forceinline__ uint32_t smem_u32(const void* p) {
    uint32_t a;
    asm("{ .reg .u64 t; cvta.to.shared.u64 t, %1; cvt.u32.u64 %0, t; }" : "=r"(a) : "l"(p));
    return a;
}
__device__ __forceinline__ void cp16(uint32_t dst, const void* src) {
    asm volatile("cp.async.cg.shared.global [%0], [%1], 16;" :: "r"(dst), "l"(src) : "memory");
}
#define CP_COMMIT() asm volatile("cp.async.commit_group;" ::: "memory")

__device__ __forceinline__ void mma1688_tf32(float* d, const uint32_t* a, const uint32_t* b) {
    asm volatile(
        "mma.sync.aligned.m16n8k8.row.col.f32.tf32.tf32.f32 "
        "{%0,%1,%2,%3}, {%4,%5,%6,%7}, {%8,%9}, {%0,%1,%2,%3};"
        : "+f"(d[0]), "+f"(d[1]), "+f"(d[2]), "+f"(d[3])
        : "r"(a[0]), "r"(a[1]), "r"(a[2]), "r"(a[3]), "r"(b[0]), "r"(b[1]));
}
__device__ __forceinline__ uint32_t cvt_tf32(float f) {
    uint32_t r;
    asm("cvt.rna.tf32.f32 %0, %1;" : "=r"(r) : "f"(f));
    return r;
}
__device__ __forceinline__ uint32_t lds32(uint32_t a) {
    uint32_t r;
    asm volatile("ld.shared.b32 %0, [%1];" : "=r"(r) : "r"(a));
    return r;
}

// ===========================================================================
// Kernel A (tf32, 16 stages x K16, 4 buffers): hyper GEMM + fused BN +
// DIRECT (b,uv,s,f) output. 2 CTAs/SM. (proven R12)
// ===========================================================================
#define H2_APW 268
#define H2_BPW 264
#define H2_RB  34304
#define H2_BBUF 16896
#define H2_SMEM 101888

__global__ __launch_bounds__(512, 2) void hyper_tf32_kernel(
    const float* __restrict__ z, const float* __restrict__ dw,
    const float* __restrict__ db, const float* __restrict__ gamma,
    const float* __restrict__ beta)
{
    extern __shared__ char hs[];
    const uint32_t sb = smem_u32(hs);
    const int tid = threadIdx.x, wid = tid >> 5, lane = tid & 31;
    const int n0 = blockIdx.x * 256;
    const int wn0 = wid * 16;
    const int g = lane >> 2, tig = lane & 3;

    auto issue = [&](int s) {
#pragma unroll
        for (int i = 0; i < 2; i++) {
            int chunk = i * 512 + tid;
            int k = chunk >> 6, seg = chunk & 63;
            cp16(sb + H2_RB + (uint32_t)(s & 3) * H2_BBUF + k * (H2_BPW * 4) + seg * 16,
                 dw + (size_t)(s * 16 + k) * NB + n0 + seg * 4);
        }
        CP_COMMIT();
    };
    issue(0);
    issue(1);
    issue(2);

    {
        const int m = tid >> 4, k0 = (tid & 15) * 16;
        const float4* zsrc = reinterpret_cast<const float4*>(z + m * ZD + k0);
        uint32_t* arow = reinterpret_cast<uint32_t*>(hs) + m * H2_APW + k0;
#pragma unroll
        for (int j = 0; j < 4; j++) {
            float4 v = zsrc[j];
            arow[j * 4 + 0] = cvt_tf32(v.x);
            arow[j * 4 + 1] = cvt_tf32(v.y);
            arow[j * 4 + 2] = cvt_tf32(v.z);
            arow[j * 4 + 3] = cvt_tf32(v.w);
        }
    }

    float d[2][2][4];
#pragma unroll
    for (int mt = 0; mt < 2; mt++)
#pragma unroll
        for (int nt = 0; nt < 2; nt++)
#pragma unroll
            for (int e = 0; e < 4; e++) d[mt][nt][e] = 0.0f;

    const uint32_t abase = sb + (uint32_t)(g * H2_APW + tig) * 4;

    for (int s = 0; s < 16; s++) {
        if (s < 14)      asm volatile("cp.async.wait_group 2;" ::: "memory");
        else if (s == 14) asm volatile("cp.async.wait_group 1;" ::: "memory");
        else              asm volatile("cp.async.wait_group 0;" ::: "memory");
        __syncthreads();
        if (s + 3 < 16) issue(s + 3);

        const uint32_t bbuf = sb + H2_RB + (uint32_t)(s & 3) * H2_BBUF;
#pragma unroll
        for (int kk = 0; kk < 2; kk++) {
            const uint32_t acol = (uint32_t)(s * 16 + kk * 8) * 4;
            uint32_t a[2][4], bfr[2][2];
#pragma unroll
            for (int mt = 0; mt < 2; mt++) {
                const uint32_t ab = abase + (uint32_t)(mt * 16 * H2_APW) * 4 + acol;
                a[mt][0] = lds32(ab);
                a[mt][1] = lds32(ab + (uint32_t)(8 * H2_APW) * 4);
                a[mt][2] = lds32(ab + 16);
                a[mt][3] = lds32(ab + (uint32_t)(8 * H2_APW) * 4 + 16);
            }
#pragma unroll
            for (int nt = 0; nt < 2; nt++) {
                const uint32_t bb = bbuf + (uint32_t)((kk * 8 + tig) * H2_BPW
                                                      + wn0 + nt * 8 + g) * 4;
                bfr[nt][0] = cvt_tf32(__uint_as_float(lds32(bb)));
                bfr[nt][1] = cvt_tf32(__uint_as_float(lds32(bb + (uint32_t)(4 * H2_BPW) * 4)));
            }
#pragma unroll
            for (int mt = 0; mt < 2; mt++)
#pragma unroll
                for (int nt = 0; nt < 2; nt++)
                    mma1688_tf32(d[mt][nt], a[mt], bfr[nt]);
        }
    }

    const int jc = n0 + wn0 + 2 * tig;
    float2 db2[2], g2[2], bt2[2];
#pragma unroll
    for (int nt = 0; nt < 2; nt++) {
        db2[nt] = *reinterpret_cast<const float2*>(db + jc + nt * 8);
        g2[nt]  = *reinterpret_cast<const float2*>(gamma + jc + nt * 8);
        bt2[nt] = *reinterpret_cast<const float2*>(beta + jc + nt * 8);
    }
#pragma unroll
    for (int mt = 0; mt < 2; mt++)
#pragma unroll
        for (int nt = 0; nt < 2; nt++) {
            d[mt][nt][0] = fmaxf(d[mt][nt][0] + db2[nt].x, 0.0f);
            d[mt][nt][1] = fmaxf(d[mt][nt][1] + db2[nt].y, 0.0f);
            d[mt][nt][2] = fmaxf(d[mt][nt][2] + db2[nt].x, 0.0f);
            d[mt][nt][3] = fmaxf(d[mt][nt][3] + db2[nt].y, 0.0f);
        }

    float sm[2][2], sq[2][2];
#pragma unroll
    for (int nt = 0; nt < 2; nt++)
#pragma unroll
        for (int c = 0; c < 2; c++) {
            float s1 = d[0][nt][c] + d[0][nt][c + 2] + d[1][nt][c] + d[1][nt][c + 2];
            float q1 = d[0][nt][c] * d[0][nt][c] + d[0][nt][c + 2] * d[0][nt][c + 2]
                     + d[1][nt][c] * d[1][nt][c] + d[1][nt][c + 2] * d[1][nt][c + 2];
#pragma unroll
            for (int o = 4; o < 32; o <<= 1) {
                s1 += __shfl_xor_sync(0xffffffffu, s1, o);
                q1 += __shfl_xor_sync(0xffffffffu, q1, o);
            }
            sm[nt][c] = s1 * (1.0f / 32.0f);
            float var = fmaxf(q1 * (1.0f / 32.0f) - sm[nt][c] * sm[nt][c], 0.0f);
            float gm = (c == 0) ? ((nt == 0) ? g2[0].x : g2[1].x)
                                : ((nt == 0) ? g2[0].y : g2[1].y);
            sq[nt][c] = gm / (sqrtf(var) + 1e-6f);
        }

    float* sOut = reinterpret_cast<float*>(hs + H2_RB);
    const int jl0 = wn0 + 2 * tig;
#pragma unroll
    for (int mt = 0; mt < 2; mt++)
#pragma unroll
        for (int nt = 0; nt < 2; nt++) {
            const int jl = jl0 + nt * 8;
            float2 o0 = make_float2((d[mt][nt][0] - sm[nt][0]) * sq[nt][0] + bt2[nt].x,
                                    (d[mt][nt][1] - sm[nt][1]) * sq[nt][1] + bt2[nt].y);
            float2 o1 = make_float2((d[mt][nt][2] - sm[nt][0]) * sq[nt][0] + bt2[nt].x,
                                    (d[mt][nt][3] - sm[nt][1]) * sq[nt][1] + bt2[nt].y);
            *reinterpret_cast<float2*>(&sOut[(mt * 16 + g) * 266 + jl]) = o0;
            *reinterpret_cast<float2*>(&sOut[(mt * 16 + g + 8) * 266 + jl]) = o1;
        }

    int* tbl = reinterpret_cast<int*>(hs + H2_RB + 40960);
    const int r0 = n0 % 1152, s0 = n0 / 1152;
    if (tid == 0) {
        int acc = 0;
        for (int uv = 0; uv < 9; uv++) {
            tbl[uv] = acc;
            int cnt = (n0 + 264 - uv) / 9 - (n0 + 8 - uv) / 9;
            tbl[10 + uv] = (r0 + 8 - uv) / 9;
            acc += cnt;
        }
        tbl[9] = acc;
    }
    __syncthreads();

    for (int e = tid; e < 8192; e += 512) {
        int m = e >> 8, rem = e & 255;
        int uv = 0;
#pragma unroll
        for (int q = 1; q < 9; q++) uv += (rem >= tbl[q]);
        int fi = rem - tbl[uv];
        int fidx = tbl[10 + uv] + fi;
        int s = s0, f = fidx;
        if (fidx >= 128) { f = fidx - 128; s = s0 + 1; }
        int r = f * 9 + uv;
        int jloc = (s - s0) * 1152 + r - r0;
        g_W2[(((size_t)m * 9 + uv) * 128 + s) * 128 + f] = sOut[m * 266 + jloc];
    }
}

// ===========================================================================
// Kernel X: x -> padded channel-last tf32-rounded fp32 (b, row34, col36, s128)
// ===========================================================================
__global__ __launch_bounds__(256) void xprep_kernel(const float* __restrict__ x)
{
    __shared__ float sX[128 * 33];
    const int b = blockIdx.y, p = blockIdx.x, tid = threadIdx.x;
    for (int i = tid; i < 4096; i += 256) {
        int s = i >> 5, q = i & 31;
        sX[s * 33 + q] = x[(((size_t)(b * 128 + s)) * 32 + p) * 32 + q];
    }
    __syncthreads();
    for (int i = tid; i < 4096; i += 256) {
        int s = i & 127, q = i >> 7;
        float v = sX[s * 33 + q];
        size_t o = (((size_t)b * 34 + (p + 1)) * 36 + (q + 1)) * 128 + s;
        g_xt[o] = __uint_as_float(cvt_tf32(v));
    }
}

// ===========================================================================
// Kernel C (v6, tf32): 256 CTAs (4-row px blocks) x 256 thr, 2 CTAs/SM.
//   Warp tile 32f x 64px (8 warps: 4 f-groups x 2 px-groups). K-chunk 32,
//   36 stages; x-slice [6r][36c][64s] resident per 2 s-chunks (reload @18).
// smem: XS @0 (58752) | A bufs @58752: 3 x 17408 -> 110976 B (2 CTAs/SM)
// ===========================================================================
#define XSP    272          // 68 floats
#define XSSZ   58752
#define APB    544          // A row pitch bytes (136 floats)
#define ABUF   17408
#define CSMEM  110976

__global__ __launch_bounds__(256, 2) void conv_mma_kernel(
    const float* __restrict__ xin,
    const float* __restrict__ bias,
    float* __restrict__ out)
{
    extern __shared__ char smem[];
    const uint32_t sb = smem_u32(smem);
    const int tid = threadIdx.x, wid = tid >> 5, lane = tid & 31;
    const int b = blockIdx.y, pb = blockIdx.x;   // pixel rows pb*4..pb*4+3
    const int f0 = (wid >> 1) * 32;
    const int px0 = (wid & 1) * 64;
    const int g = lane >> 2, tig = lane & 3;

    float d[2][8][4];
#pragma unroll
    for (int i = 0; i < 2; i++)
#pragma unroll
        for (int j = 0; j < 8; j++)
#pragma unroll
            for (int e = 0; e < 4; e++) d[i][j][e] = 0.0f;

    uint32_t bbase[8];
#pragma unroll
    for (int nt = 0; nt < 8; nt++) {
        int prow = (px0 >> 5) + (nt >> 2);
        int pcol = (nt & 3) * 8 + g;
        bbase[nt] = (uint32_t)((prow * 36 + pcol) * XSP + tig * 4);
    }

    auto load_xslice = [&](int ch) {      // ch: 0 -> s0..63, 1 -> s64..127
        for (int i = tid; i < 3456; i += 256) {
            int r = i / 576, rem = i % 576;
            int c = rem >> 4, seg = rem & 15;
            const float* src = g_xt +
                (((size_t)(b * 34 + pb * 4 + r)) * 36 + c) * 128 + ch * 64 + seg * 4;
            cp16(sb + (uint32_t)((r * 36 + c) * XSP + seg * 16), src);
        }
        CP_COMMIT();
    };

    auto issueA = [&](int ast) {
        const int uv = ast % 9, sc = ast / 9;          // sc 0..3 (32 s each)
        const uint32_t base = sb + XSSZ + (uint32_t)(ast % 3) * ABUF;
        const float* srcb = g_W2 + ((size_t)(b * 9 + uv) * 128 + sc * 32) * 128;
#pragma unroll
        for (int i = 0; i < 4; i++) {
            int c2 = i * 256 + tid;                    // 0..1023
            int srow = c2 >> 5, seg = c2 & 31;
            cp16(base + (uint32_t)(srow * APB + seg * 16), srcb + srow * 128 + seg * 4);
        }
        CP_COMMIT();
    };

    load_xslice(0);
    issueA(0);
    issueA(1);

    for (int ast = 0; ast < 36; ast++) {
        if (ast == 18 || ast == 35) asm volatile("cp.async.wait_group 0;" ::: "memory");
        else                        asm volatile("cp.async.wait_group 1;" ::: "memory");
        __syncthreads();
        if (ast + 2 < 36) issueA(ast + 2);

        const int uv = ast % 9, sc = ast / 9;
        const int u = uv / 3, v = uv - 3 * u;
        const uint32_t uvoff = (uint32_t)((u * 36 + v) * XSP) + (uint32_t)((sc & 1) * 128);
        const uint32_t baseA = sb + XSSZ + (uint32_t)(ast % 3) * ABUF;
        const uint32_t abase0 = baseA + (uint32_t)(tig * APB + (f0 + g) * 4);

#pragma unroll
        for (int kk = 0; kk < 4; kk++) {
            const uint32_t ab = abase0 + (uint32_t)(kk * 8 * APB);
            uint32_t a[2][4];
#pragma unroll
            for (int mt = 0; mt < 2; mt++) {
                const uint32_t abm = ab + (uint32_t)(mt * 64);
                a[mt][0] = lds32(abm);
                a[mt][1] = lds32(abm + 32);
                a[mt][2] = lds32(abm + 4 * APB);
                a[mt][3] = lds32(abm + 4 * APB + 32);
            }
            const uint32_t ko = (uint32_t)kk * 32;
#pragma unroll
            for (int nt = 0; nt < 8; nt++) {
                uint32_t bfr[2];
                const uint32_t bbv = sb + bbase[nt] + uvoff + ko;
                bfr[0] = lds32(bbv);
                bfr[1] = lds32(bbv + 16);
#pragma unroll
                for (int mt = 0; mt < 2; mt++)
                    mma1688_tf32(d[mt][nt], a[mt], bfr);
            }
        }

        if (ast == 17) {            // slice 0 (s0..63) fully consumed
            __syncthreads();
            load_xslice(1);
        }
    }

    // ---- epilogue: + residual + bias ----
    const int tc = lane & 3;
#pragma unroll
    for (int i = 0; i < 2; i++) {
        const int fr0 = f0 + i * 16 + g;
        const float bv0 = __ldg(&bias[fr0]);
        const float bv1 = __ldg(&bias[fr0 + 8]);
#pragma unroll
        for (int j = 0; j < 8; j++) {
            const int pix = pb * 128 + px0 + j * 8 + tc * 2;
            {
                size_t o = ((size_t)(b * 128 + fr0)) * 1024 + pix;
                float2 xr = *reinterpret_cast<const float2*>(xin + o);
                float2 w = make_float2(d[i][j][0] + xr.x + bv0,
                                       d[i][j][1] + xr.y + bv0);
                *reinterpret_cast<float2*>(out + o) = w;
            }
            {
                size_t o = ((size_t)(b * 128 + fr0 + 8)) * 1024 + pix;
                float2 xr = *reinterpret_cast<const float2*>(xin + o);
                float2 w = make_float2(d[i][j][2] + xr.x + bv1,
                                       d[i][j][3] + xr.y + bv1);
                *reinterpret_cast<float2*>(out + o) = w;
            }
        }
    }
}

// ===========================================================================
extern "C" void kernel_launch(void* const* d_in, const int* in_sizes, int n_in,
                              void* d_out, int out_size)
{
    (void)in_sizes; (void)n_in; (void)out_size;
    const float* x     = (const float*)d_in[0];
    const float* z     = (const float*)d_in[1];
    const float* dw    = (const float*)d_in[2];
    const float* db    = (const float*)d_in[3];
    const float* gamma = (const float*)d_in[4];
    const float* beta  = (const float*)d_in[5];
    const float* bconv = (const float*)d_in[6];
    float* out = (float*)d_out;

    cudaFuncSetAttribute(hyper_tf32_kernel,
                         cudaFuncAttributeMaxDynamicSharedMemorySize, H2_SMEM);
    cudaFuncSetAttribute(conv_mma_kernel,
                         cudaFuncAttributeMaxDynamicSharedMemorySize, CSMEM);

    hyper_tf32_kernel<<<NB / 256, 512, H2_SMEM>>>(z, dw, db, gamma, beta);
    xprep_kernel<<<dim3(32, BATCH), 256>>>(x);
    conv_mma_kernel<<<dim3(8, BATCH), 256, CSMEM>>>(x, bconv, out);
}

// round 14
// speedup vs baseline: 1.0316x; 1.0316x over previous
#include <cuda_runtime.h>
#include <cuda_bf16.h>
#include <cstdint>

#define CIN   128
#define COUT  128
#define KHW   9
#define NB    (CIN*COUT*KHW)   // 147456
#define ZD    256
#define BATCH 32
#define HW    32
#define HW2   (HW*HW)

// ---------------- scratch (device globals; no allocs allowed) ----------------
__device__ __align__(1024) float g_W2[BATCH * 9 * 128 * 128];      // tf32-rounded (b, uv, s, f)
__device__ __align__(1024) float g_xt[BATCH * 34 * 36 * 128];      // tf32-rounded (b,row,col,s); pad stays 0

// ---------------- helpers ----------------
__device__ __forceinline__ uint32_t smem_u32(const void* p) {
    uint32_t a;
    asm("{ .reg .u64 t; cvta.to.shared.u64 t, %1; cvt.u32.u64 %0, t; }" : "=r"(a) : "l"(p));
    return a;
}
__device__ __forceinline__ void cp16(uint32_t dst, const void* src) {
    asm volatile("cp.async.cg.shared.global [%0], [%1], 16;" :: "r"(dst), "l"(src) : "memory");
}
#define CP_COMMIT() asm volatile("cp.async.commit_group;" ::: "memory")

__device__ __forceinline__ void mma1688_tf32(float* d, const uint32_t* a, const uint32_t* b) {
    asm volatile(
        "mma.sync.aligned.m16n8k8.row.col.f32.tf32.tf32.f32 "
        "{%0,%1,%2,%3}, {%4,%5,%6,%7}, {%8,%9}, {%0,%1,%2,%3};"
        : "+f"(d[0]), "+f"(d[1]), "+f"(d[2]), "+f"(d[3])
        : "r"(a[0]), "r"(a[1]), "r"(a[2]), "r"(a[3]), "r"(b[0]), "r"(b[1]));
}
__device__ __forceinline__ uint32_t cvt_tf32(float f) {
    uint32_t r;
    asm("cvt.rna.tf32.f32 %0, %1;" : "=r"(r) : "f"(f));
    return r;
}
__device__ __forceinline__ uint32_t lds32(uint32_t a) {
    uint32_t r;
    asm volatile("ld.shared.b32 %0, [%1];" : "=r"(r) : "r"(a));
    return r;
}

// ===========================================================================
// Kernel A (tf32, warp-private B stripes, NO mainloop barriers):
//   M=32, K=256, N=256 per CTA (576 CTAs), 512 thr, 2 CTAs/SM.
//   Each warp owns cols wn0..wn0+15: private 3-buffer ring of [16k][16n]
//   stripes (pitch 24 fl, conflict-free), own cp.async groups, per-thread
//   wait_group -> warps fully decoupled across the 16 K-stages.
// smem: A @0 32x268 fp32 (34304B) | stripes @34304: 16w x 3buf x 1536B
// epilogue reuses stripe region: sOut 32x266 fl @34304, tables @+40960
// ===========================================================================
#define H2_APW 268
#define H2_RB  34304
#define H2_SMEM 108032

__global__ __launch_bounds__(512, 2) void hyper_tf32_kernel(
    const float* __restrict__ z, const float* __restrict__ dw,
    const float* __restrict__ db, const float* __restrict__ gamma,
    const float* __restrict__ beta)
{
    extern __shared__ char hs[];
    const uint32_t sb = smem_u32(hs);
    const int tid = threadIdx.x, wid = tid >> 5, lane = tid & 31;
    const int n0 = blockIdx.x * 256;
    const int wn0 = wid * 16;
    const int g = lane >> 2, tig = lane & 3;

    const uint32_t bstripe = sb + H2_RB + (uint32_t)(wid * 3) * 1536;

    auto issue = [&](int s) {
        const uint32_t base = bstripe + (uint32_t)(s % 3) * 1536;
#pragma unroll
        for (int i = 0; i < 2; i++) {
            int chunk = i * 32 + lane;
            int row = chunk >> 2, seg = chunk & 3;
            cp16(base + (uint32_t)(row * 96 + seg * 16),
                 dw + (size_t)(s * 16 + row) * NB + n0 + wn0 + seg * 4);
        }
        CP_COMMIT();
    };
    issue(0);
    issue(1);
    issue(2);

    // A (z) -> tf32 (rna) smem [m=32][k=256]
    {
        const int m = tid >> 4, k0 = (tid & 15) * 16;
        const float4* zsrc = reinterpret_cast<const float4*>(z + m * ZD + k0);
        uint32_t* arow = reinterpret_cast<uint32_t*>(hs) + m * H2_APW + k0;
#pragma unroll
        for (int j = 0; j < 4; j++) {
            float4 v = zsrc[j];
            arow[j * 4 + 0] = cvt_tf32(v.x);
            arow[j * 4 + 1] = cvt_tf32(v.y);
            arow[j * 4 + 2] = cvt_tf32(v.z);
            arow[j * 4 + 3] = cvt_tf32(v.w);
        }
    }
    __syncthreads();   // A visible to all warps; from here warps run free

    float d[2][2][4];
#pragma unroll
    for (int mt = 0; mt < 2; mt++)
#pragma unroll
        for (int nt = 0; nt < 2; nt++)
#pragma unroll
            for (int e = 0; e < 4; e++) d[mt][nt][e] = 0.0f;

    const uint32_t abase = sb + (uint32_t)(g * H2_APW + tig) * 4;

    for (int s = 0; s < 16; s++) {
        if (s < 14)      asm volatile("cp.async.wait_group 2;" ::: "memory");
        else if (s == 14) asm volatile("cp.async.wait_group 1;" ::: "memory");
        else              asm volatile("cp.async.wait_group 0;" ::: "memory");

        const uint32_t bbuf = bstripe + (uint32_t)(s % 3) * 1536;
#pragma unroll
        for (int kk = 0; kk < 2; kk++) {
            const uint32_t acol = (uint32_t)(s * 16 + kk * 8) * 4;
            uint32_t a[2][4], bfr[2][2];
#pragma unroll
            for (int mt = 0; mt < 2; mt++) {
                const uint32_t ab = abase + (uint32_t)(mt * 16 * H2_APW) * 4 + acol;
                a[mt][0] = lds32(ab);
                a[mt][1] = lds32(ab + (uint32_t)(8 * H2_APW) * 4);
                a[mt][2] = lds32(ab + 16);
                a[mt][3] = lds32(ab + (uint32_t)(8 * H2_APW) * 4 + 16);
            }
#pragma unroll
            for (int nt = 0; nt < 2; nt++) {
                const uint32_t bb = bbuf + (uint32_t)(((kk * 8 + tig) * 24 + nt * 8 + g)) * 4;
                bfr[nt][0] = cvt_tf32(__uint_as_float(lds32(bb)));
                bfr[nt][1] = cvt_tf32(__uint_as_float(lds32(bb + 4 * 24 * 4)));
            }
#pragma unroll
            for (int mt = 0; mt < 2; mt++)
#pragma unroll
                for (int nt = 0; nt < 2; nt++)
                    mma1688_tf32(d[mt][nt], a[mt], bfr[nt]);
        }
        if (s + 3 < 16) issue(s + 3);   // after compute: reuses buffer s%3
    }

    // ---- epilogue: relu + BN over 32 batch rows (warp-local) ----
    const int jc = n0 + wn0 + 2 * tig;
    float2 db2[2], g2[2], bt2[2];
#pragma unroll
    for (int nt = 0; nt < 2; nt++) {
        db2[nt] = *reinterpret_cast<const float2*>(db + jc + nt * 8);
        g2[nt]  = *reinterpret_cast<const float2*>(gamma + jc + nt * 8);
        bt2[nt] = *reinterpret_cast<const float2*>(beta + jc + nt * 8);
    }
#pragma unroll
    for (int mt = 0; mt < 2; mt++)
#pragma unroll
        for (int nt = 0; nt < 2; nt++) {
            d[mt][nt][0] = fmaxf(d[mt][nt][0] + db2[nt].x, 0.0f);
            d[mt][nt][1] = fmaxf(d[mt][nt][1] + db2[nt].y, 0.0f);
            d[mt][nt][2] = fmaxf(d[mt][nt][2] + db2[nt].x, 0.0f);
            d[mt][nt][3] = fmaxf(d[mt][nt][3] + db2[nt].y, 0.0f);
        }

    float sm[2][2], sq[2][2];
#pragma unroll
    for (int nt = 0; nt < 2; nt++)
#pragma unroll
        for (int c = 0; c < 2; c++) {
            float s1 = d[0][nt][c] + d[0][nt][c + 2] + d[1][nt][c] + d[1][nt][c + 2];
            float q1 = d[0][nt][c] * d[0][nt][c] + d[0][nt][c + 2] * d[0][nt][c + 2]
                     + d[1][nt][c] * d[1][nt][c] + d[1][nt][c + 2] * d[1][nt][c + 2];
#pragma unroll
            for (int o = 4; o < 32; o <<= 1) {
                s1 += __shfl_xor_sync(0xffffffffu, s1, o);
                q1 += __shfl_xor_sync(0xffffffffu, q1, o);
            }
            sm[nt][c] = s1 * (1.0f / 32.0f);
            float var = fmaxf(q1 * (1.0f / 32.0f) - sm[nt][c] * sm[nt][c], 0.0f);
            float gm = (c == 0) ? ((nt == 0) ? g2[0].x : g2[1].x)
                                : ((nt == 0) ? g2[0].y : g2[1].y);
            sq[nt][c] = gm / (sqrtf(var) + 1e-6f);
        }

    __syncthreads();   // all warps done with stripe region before reuse

    float* sOut = reinterpret_cast<float*>(hs + H2_RB);
    const int jl0 = wn0 + 2 * tig;
#pragma unroll
    for (int mt = 0; mt < 2; mt++)
#pragma unroll
        for (int nt = 0; nt < 2; nt++) {
            const int jl = jl0 + nt * 8;
            float2 o0 = make_float2((d[mt][nt][0] - sm[nt][0]) * sq[nt][0] + bt2[nt].x,
                                    (d[mt][nt][1] - sm[nt][1]) * sq[nt][1] + bt2[nt].y);
            float2 o1 = make_float2((d[mt][nt][2] - sm[nt][0]) * sq[nt][0] + bt2[nt].x,
                                    (d[mt][nt][3] - sm[nt][1]) * sq[nt][1] + bt2[nt].y);
            *reinterpret_cast<float2*>(&sOut[(mt * 16 + g) * 266 + jl]) = o0;
            *reinterpret_cast<float2*>(&sOut[(mt * 16 + g + 8) * 266 + jl]) = o1;
        }

    int* tbl = reinterpret_cast<int*>(hs + H2_RB + 40960);
    const int r0 = n0 % 1152, s0 = n0 / 1152;
    if (tid == 0) {
        int acc = 0;
        for (int uv = 0; uv < 9; uv++) {
            tbl[uv] = acc;
            int cnt = (n0 + 264 - uv) / 9 - (n0 + 8 - uv) / 9;
            tbl[10 + uv] = (r0 + 8 - uv) / 9;
            acc += cnt;
        }
        tbl[9] = acc;
    }
    __syncthreads();

    for (int e = tid; e < 8192; e += 512) {
        int m = e >> 8, rem = e & 255;
        int uv = 0;
#pragma unroll
        for (int q = 1; q < 9; q++) uv += (rem >= tbl[q]);
        int fi = rem - tbl[uv];
        int fidx = tbl[10 + uv] + fi;
        int s = s0, f = fidx;
        if (fidx >= 128) { f = fidx - 128; s = s0 + 1; }
        int r = f * 9 + uv;
        int jloc = (s - s0) * 1152 + r - r0;
        g_W2[(((size_t)m * 9 + uv) * 128 + s) * 128 + f] = sOut[m * 266 + jloc];
    }
}

// ===========================================================================
// Kernel X: x -> padded channel-last tf32-rounded fp32 (b, row34, col36, s128)
// ===========================================================================
__global__ __launch_bounds__(256) void xprep_kernel(const float* __restrict__ x)
{
    __shared__ float sX[128 * 33];
    const int b = blockIdx.y, p = blockIdx.x, tid = threadIdx.x;
    for (int i = tid; i < 4096; i += 256) {
        int s = i >> 5, q = i & 31;
        sX[s * 33 + q] = x[(((size_t)(b * 128 + s)) * 32 + p) * 32 + q];
    }
    __syncthreads();
    for (int i = tid; i < 4096; i += 256) {
        int s = i & 127, q = i >> 7;
        float v = sX[s * 33 + q];
        size_t o = (((size_t)b * 34 + (p + 1)) * 36 + (q + 1)) * 128 + s;
        g_xt[o] = __uint_as_float(cvt_tf32(v));
    }
}

// ===========================================================================
// Kernel C (v5 PROVEN, tf32): conv GEMM, resident fp32 x-slice + 3-stage A
// pipeline. 128 CTAs x 512 thr. A tiles [s 64][f 128] from g_W2 (b,uv,s,f).
// ===========================================================================
#define XSP    272          // 68 floats
#define XSSZ   97920
#define APB    544          // A row pitch bytes (136 floats)
#define ABUF   34816
#define CSMEM  202368

__global__ __launch_bounds__(512, 1) void conv_mma_kernel(
    const float* __restrict__ xin,
    const float* __restrict__ bias,
    float* __restrict__ out)
{
    extern __shared__ char smem[];
    const uint32_t sb = smem_u32(smem);
    const int tid = threadIdx.x, wid = tid >> 5, lane = tid & 31;
    const int b = blockIdx.y, pb = blockIdx.x;   // pixel rows pb*8..pb*8+7
    const int f0 = (wid >> 2) * 32;
    const int px0 = (wid & 3) * 64;
    const int g = lane >> 2, tig = lane & 3;

    float d[2][8][4];
#pragma unroll
    for (int i = 0; i < 2; i++)
#pragma unroll
        for (int j = 0; j < 8; j++)
#pragma unroll
            for (int e = 0; e < 4; e++) d[i][j][e] = 0.0f;

    uint32_t bbase[8];
#pragma unroll
    for (int nt = 0; nt < 8; nt++) {
        int prow = (px0 >> 5) + (nt >> 2);
        int pcol = (nt & 3) * 8 + g;
        bbase[nt] = (uint32_t)((prow * 36 + pcol) * XSP + tig * 4);
    }

    auto load_xslice = [&](int sc) {
        for (int i = tid; i < 5760; i += 512) {
            int r = i / 576, rem = i % 576;
            int c = rem >> 4, seg = rem & 15;
            const float* src = g_xt +
                (((size_t)(b * 34 + pb * 8 + r)) * 36 + c) * 128 + sc * 64 + seg * 4;
            cp16(sb + (uint32_t)((r * 36 + c) * XSP + seg * 16), src);
        }
        CP_COMMIT();
    };

    auto issueA = [&](int ast) {
        const int uv = ast % 9, sc = ast / 9;
        const uint32_t base = sb + XSSZ + (uint32_t)(ast % 3) * ABUF;
        const float* srcb = g_W2 + ((size_t)(b * 9 + uv) * 128 + sc * 64) * 128;
#pragma unroll
        for (int i = 0; i < 4; i++) {
            int c2 = i * 512 + tid;
            int srow = c2 >> 5, seg = c2 & 31;
            cp16(base + (uint32_t)(srow * APB + seg * 16), srcb + srow * 128 + seg * 4);
        }
        CP_COMMIT();
    };

    load_xslice(0);
    issueA(0);
    issueA(1);

    for (int ast = 0; ast < 18; ast++) {
        if (ast == 9 || ast == 17) asm volatile("cp.async.wait_group 0;" ::: "memory");
        else                       asm volatile("cp.async.wait_group 1;" ::: "memory");
        __syncthreads();
        if (ast + 2 < 18) issueA(ast + 2);

        const int uv = ast % 9;
        const int u = uv / 3, v = uv - 3 * u;
        const uint32_t uvoff = (uint32_t)((u * 36 + v) * XSP);
        const uint32_t baseA = sb + XSSZ + (uint32_t)(ast % 3) * ABUF;
        const uint32_t abase0 = baseA + (uint32_t)(tig * APB + (f0 + g) * 4);

#pragma unroll
        for (int kk = 0; kk < 8; kk++) {
            const uint32_t ab = abase0 + (uint32_t)(kk * 8 * APB);
            uint32_t a[2][4];
#pragma unroll
            for (int mt = 0; mt < 2; mt++) {
                const uint32_t abm = ab + (uint32_t)(mt * 64);
                a[mt][0] = lds32(abm);
                a[mt][1] = lds32(abm + 32);
                a[mt][2] = lds32(abm + 4 * APB);
                a[mt][3] = lds32(abm + 4 * APB + 32);
            }
            const uint32_t ko = (uint32_t)kk * 32;
#pragma unroll
            for (int nt = 0; nt < 8; nt++) {
                uint32_t bfr[2];
                const uint32_t bbv = sb + bbase[nt] + uvoff + ko;
                bfr[0] = lds32(bbv);
                bfr[1] = lds32(bbv + 16);
#pragma unroll
                for (int mt = 0; mt < 2; mt++)
                    mma1688_tf32(d[mt][nt], a[mt], bfr);
            }
        }

        if (ast == 8) {
            __syncthreads();
            load_xslice(1);
        }
    }

    // ---- epilogue: + residual + bias ----
    const int tc = lane & 3;
#pragma unroll
    for (int i = 0; i < 2; i++) {
        const int fr0 = f0 + i * 16 + g;
        const float bv0 = __ldg(&bias[fr0]);
        const float bv1 = __ldg(&bias[fr0 + 8]);
#pragma unroll
        for (int j = 0; j < 8; j++) {
            const int pix = pb * 256 + px0 + j * 8 + tc * 2;
            {
                size_t o = ((size_t)(b * 128 + fr0)) * 1024 + pix;
                float2 xr = *reinterpret_cast<const float2*>(xin + o);
                float2 w = make_float2(d[i][j][0] + xr.x + bv0,
                                       d[i][j][1] + xr.y + bv0);
                *reinterpret_cast<float2*>(out + o) = w;
            }
            {
                size_t o = ((size_t)(b * 128 + fr0 + 8)) * 1024 + pix;
                float2 xr = *reinterpret_cast<const float2*>(xin + o);
                float2 w = make_float2(d[i][j][2] + xr.x + bv1,
                                       d[i][j][3] + xr.y + bv1);
                *reinterpret_cast<float2*>(out + o) = w;
            }
        }
    }
}

// ===========================================================================
extern "C" void kernel_launch(void* const* d_in, const int* in_sizes, int n_in,
                              void* d_out, int out_size)
{
    (void)in_sizes; (void)n_in; (void)out_size;
    const float* x     = (const float*)d_in[0];
    const float* z     = (const float*)d_in[1];
    const float* dw    = (const float*)d_in[2];
    const float* db    = (const float*)d_in[3];
    const float* gamma = (const float*)d_in[4];
    const float* beta  = (const float*)d_in[5];
    const float* bconv = (const float*)d_in[6];
    float* out = (float*)d_out;

    cudaFuncSetAttribute(hyper_tf32_kernel,
                         cudaFuncAttributeMaxDynamicSharedMemorySize, H2_SMEM);
    cudaFuncSetAttribute(conv_mma_kernel,
                         cudaFuncAttributeMaxDynamicSharedMemorySize, CSMEM);

    hyper_tf32_kernel<<<NB / 256, 512, H2_SMEM>>>(z, dw, db, gamma, beta);
    xprep_kernel<<<dim3(32, BATCH), 256>>>(x);
    conv_mma_kernel<<<dim3(4, BATCH), 512, CSMEM>>>(x, bconv, out);
}

// round 15
// speedup vs baseline: 1.1101x; 1.0761x over previous
#include <cuda_runtime.h>
#include <cuda_bf16.h>
#include <cstdint>

#define CIN   128
#define COUT  128
#define KHW   9
#define NB    (CIN*COUT*KHW)   // 147456
#define ZD    256
#define BATCH 32
#define HW    32
#define HW2   (HW*HW)

// ---------------- scratch (device globals; no allocs allowed) ----------------
__device__ __align__(1024) float g_W2[BATCH * 9 * 128 * 128];      // tf32-rounded (b, uv, s, f)
__device__ __align__(1024) float g_xt[BATCH * 34 * 36 * 128];      // tf32-rounded (b,row,col,s); pad stays 0

// ---------------- helpers ----------------
__device__ __forceinline__ uint32_t smem_u32(const void* p) {
    uint32_t a;
    asm("{ .reg .u64 t; cvta.to.shared.u64 t, %1; cvt.u32.u64 %0, t; }" : "=r"(a) : "l"(p));
    return a;
}
__device__ __forceinline__ void cp16(uint32_t dst, const void* src) {
    asm volatile("cp.async.cg.shared.global [%0], [%1], 16;" :: "r"(dst), "l"(src) : "memory");
}
#define CP_COMMIT() asm volatile("cp.async.commit_group;" ::: "memory")

__device__ __forceinline__ void mma1688_tf32(float* d, const uint32_t* a, const uint32_t* b) {
    asm volatile(
        "mma.sync.aligned.m16n8k8.row.col.f32.tf32.tf32.f32 "
        "{%0,%1,%2,%3}, {%4,%5,%6,%7}, {%8,%9}, {%0,%1,%2,%3};"
        : "+f"(d[0]), "+f"(d[1]), "+f"(d[2]), "+f"(d[3])
        : "r"(a[0]), "r"(a[1]), "r"(a[2]), "r"(a[3]), "r"(b[0]), "r"(b[1]));
}
__device__ __forceinline__ uint32_t cvt_tf32(float f) {
    uint32_t r;
    asm("cvt.rna.tf32.f32 %0, %1;" : "=r"(r) : "f"(f));
    return r;
}
__device__ __forceinline__ uint32_t lds32(uint32_t a) {
    uint32_t r;
    asm volatile("ld.shared.b32 %0, [%1];" : "=r"(r) : "r"(a));
    return r;
}
#define GBAR(id) asm volatile("bar.sync %0, %1;" :: "r"(id), "r"(128) : "memory")

// ===========================================================================
// Kernel A (tf32, warp-private B stripes, NO mainloop barriers) + embedded
// x-prep in the prologue (hidden under the cp.async ring fill).
//   M=32, K=256, N=256 per CTA (576 CTAs), 512 thr, 2 CTAs/SM.
// smem: A @0 32x268 fp32 (34304B; first 16896B double as xprep staging)
//       stripes @34304: 16w x 3buf x 1536B
// ===========================================================================
#define H2_APW 268
#define H2_RB  34304
#define H2_SMEM 108032

__global__ __launch_bounds__(512, 2) void hyper_tf32_kernel(
    const float* __restrict__ z, const float* __restrict__ dw,
    const float* __restrict__ db, const float* __restrict__ gamma,
    const float* __restrict__ beta, const float* __restrict__ x)
{
    extern __shared__ char hs[];
    const uint32_t sb = smem_u32(hs);
    const int tid = threadIdx.x, wid = tid >> 5, lane = tid & 31;
    const int n0 = blockIdx.x * 256;
    const int wn0 = wid * 16;
    const int g = lane >> 2, tig = lane & 3;

    const uint32_t bstripe = sb + H2_RB + (uint32_t)(wid * 3) * 1536;

    auto issue = [&](int s) {
        const uint32_t base = bstripe + (uint32_t)(s % 3) * 1536;
#pragma unroll
        for (int i = 0; i < 2; i++) {
            int chunk = i * 32 + lane;
            int row = chunk >> 2, seg = chunk & 3;
            cp16(base + (uint32_t)(row * 96 + seg * 16),
                 dw + (size_t)(s * 16 + row) * NB + n0 + wn0 + seg * 4);
        }
        CP_COMMIT();
    };
    issue(0);
    issue(1);
    issue(2);

    // ---- embedded x-prep: ~2 (b,p) columns per CTA, staged in A region ----
    {
        float* sX = reinterpret_cast<float*>(hs);        // 128 x 33 fl = 16896B
        const int p0 = (blockIdx.x * 1024) / 576;
        const int p1 = ((blockIdx.x + 1) * 1024) / 576;
        for (int pr = p0; pr < p1; pr++) {
            const int xb = pr >> 5, xp = pr & 31;
            const int row = tid >> 2, qs = (tid & 3) * 8;
            const float* src = x + ((size_t)(xb * 128 + row) * 32 + xp) * 32 + qs;
            float4 v0 = *reinterpret_cast<const float4*>(src);
            float4 v1 = *reinterpret_cast<const float4*>(src + 4);
            float* dr = &sX[row * 33 + qs];
            dr[0] = v0.x; dr[1] = v0.y; dr[2] = v0.z; dr[3] = v0.w;
            dr[4] = v1.x; dr[5] = v1.y; dr[6] = v1.z; dr[7] = v1.w;
            __syncthreads();
            const int idx = tid * 8, q = idx >> 7, s0 = idx & 127;
            float o8[8];
#pragma unroll
            for (int i = 0; i < 8; i++)
                o8[i] = __uint_as_float(cvt_tf32(sX[(s0 + i) * 33 + q]));
            float* dst = g_xt + (((size_t)xb * 34 + xp + 1) * 36 + (q + 1)) * 128 + s0;
            *reinterpret_cast<float4*>(dst)     = make_float4(o8[0], o8[1], o8[2], o8[3]);
            *reinterpret_cast<float4*>(dst + 4) = make_float4(o8[4], o8[5], o8[6], o8[7]);
            __syncthreads();
        }
    }

    // A (z) -> tf32 (rna) smem [m=32][k=256]
    {
        const int m = tid >> 4, k0 = (tid & 15) * 16;
        const float4* zsrc = reinterpret_cast<const float4*>(z + m * ZD + k0);
        uint32_t* arow = reinterpret_cast<uint32_t*>(hs) + m * H2_APW + k0;
#pragma unroll
        for (int j = 0; j < 4; j++) {
            float4 v = zsrc[j];
            arow[j * 4 + 0] = cvt_tf32(v.x);
            arow[j * 4 + 1] = cvt_tf32(v.y);
            arow[j * 4 + 2] = cvt_tf32(v.z);
            arow[j * 4 + 3] = cvt_tf32(v.w);
        }
    }
    __syncthreads();   // A visible; from here warps run free

    float d[2][2][4];
#pragma unroll
    for (int mt = 0; mt < 2; mt++)
#pragma unroll
        for (int nt = 0; nt < 2; nt++)
#pragma unroll
            for (int e = 0; e < 4; e++) d[mt][nt][e] = 0.0f;

    const uint32_t abase = sb + (uint32_t)(g * H2_APW + tig) * 4;

    for (int s = 0; s < 16; s++) {
        if (s < 14)      asm volatile("cp.async.wait_group 2;" ::: "memory");
        else if (s == 14) asm volatile("cp.async.wait_group 1;" ::: "memory");
        else              asm volatile("cp.async.wait_group 0;" ::: "memory");

        const uint32_t bbuf = bstripe + (uint32_t)(s % 3) * 1536;
#pragma unroll
        for (int kk = 0; kk < 2; kk++) {
            const uint32_t acol = (uint32_t)(s * 16 + kk * 8) * 4;
            uint32_t a[2][4], bfr[2][2];
#pragma unroll
            for (int mt = 0; mt < 2; mt++) {
                const uint32_t ab = abase + (uint32_t)(mt * 16 * H2_APW) * 4 + acol;
                a[mt][0] = lds32(ab);
                a[mt][1] = lds32(ab + (uint32_t)(8 * H2_APW) * 4);
                a[mt][2] = lds32(ab + 16);
                a[mt][3] = lds32(ab + (uint32_t)(8 * H2_APW) * 4 + 16);
            }
#pragma unroll
            for (int nt = 0; nt < 2; nt++) {
                const uint32_t bb = bbuf + (uint32_t)(((kk * 8 + tig) * 24 + nt * 8 + g)) * 4;
                bfr[nt][0] = cvt_tf32(__uint_as_float(lds32(bb)));
                bfr[nt][1] = cvt_tf32(__uint_as_float(lds32(bb + 4 * 24 * 4)));
            }
#pragma unroll
            for (int mt = 0; mt < 2; mt++)
#pragma unroll
                for (int nt = 0; nt < 2; nt++)
                    mma1688_tf32(d[mt][nt], a[mt], bfr[nt]);
        }
        if (s + 3 < 16) issue(s + 3);
    }

    // ---- epilogue: relu + BN over 32 batch rows (warp-local) ----
    const int jc = n0 + wn0 + 2 * tig;
    float2 db2[2], g2[2], bt2[2];
#pragma unroll
    for (int nt = 0; nt < 2; nt++) {
        db2[nt] = *reinterpret_cast<const float2*>(db + jc + nt * 8);
        g2[nt]  = *reinterpret_cast<const float2*>(gamma + jc + nt * 8);
        bt2[nt] = *reinterpret_cast<const float2*>(beta + jc + nt * 8);
    }
#pragma unroll
    for (int mt = 0; mt < 2; mt++)
#pragma unroll
        for (int nt = 0; nt < 2; nt++) {
            d[mt][nt][0] = fmaxf(d[mt][nt][0] + db2[nt].x, 0.0f);
            d[mt][nt][1] = fmaxf(d[mt][nt][1] + db2[nt].y, 0.0f);
            d[mt][nt][2] = fmaxf(d[mt][nt][2] + db2[nt].x, 0.0f);
            d[mt][nt][3] = fmaxf(d[mt][nt][3] + db2[nt].y, 0.0f);
        }

    float sm[2][2], sq[2][2];
#pragma unroll
    for (int nt = 0; nt < 2; nt++)
#pragma unroll
        for (int c = 0; c < 2; c++) {
            float s1 = d[0][nt][c] + d[0][nt][c + 2] + d[1][nt][c] + d[1][nt][c + 2];
            float q1 = d[0][nt][c] * d[0][nt][c] + d[0][nt][c + 2] * d[0][nt][c + 2]
                     + d[1][nt][c] * d[1][nt][c] + d[1][nt][c + 2] * d[1][nt][c + 2];
#pragma unroll
            for (int o = 4; o < 32; o <<= 1) {
                s1 += __shfl_xor_sync(0xffffffffu, s1, o);
                q1 += __shfl_xor_sync(0xffffffffu, q1, o);
            }
            sm[nt][c] = s1 * (1.0f / 32.0f);
            float var = fmaxf(q1 * (1.0f / 32.0f) - sm[nt][c] * sm[nt][c], 0.0f);
            float gm = (c == 0) ? ((nt == 0) ? g2[0].x : g2[1].x)
                                : ((nt == 0) ? g2[0].y : g2[1].y);
            sq[nt][c] = gm / (sqrtf(var) + 1e-6f);
        }

    __syncthreads();   // all warps done with stripe region before reuse

    float* sOut = reinterpret_cast<float*>(hs + H2_RB);
    const int jl0 = wn0 + 2 * tig;
#pragma unroll
    for (int mt = 0; mt < 2; mt++)
#pragma unroll
        for (int nt = 0; nt < 2; nt++) {
            const int jl = jl0 + nt * 8;
            float2 o0 = make_float2((d[mt][nt][0] - sm[nt][0]) * sq[nt][0] + bt2[nt].x,
                                    (d[mt][nt][1] - sm[nt][1]) * sq[nt][1] + bt2[nt].y);
            float2 o1 = make_float2((d[mt][nt][2] - sm[nt][0]) * sq[nt][0] + bt2[nt].x,
                                    (d[mt][nt][3] - sm[nt][1]) * sq[nt][1] + bt2[nt].y);
            *reinterpret_cast<float2*>(&sOut[(mt * 16 + g) * 266 + jl]) = o0;
            *reinterpret_cast<float2*>(&sOut[(mt * 16 + g + 8) * 266 + jl]) = o1;
        }

    int* tbl = reinterpret_cast<int*>(hs + H2_RB + 40960);
    const int r0 = n0 % 1152, s0 = n0 / 1152;
    if (tid == 0) {
        int acc = 0;
        for (int uv = 0; uv < 9; uv++) {
            tbl[uv] = acc;
            int cnt = (n0 + 264 - uv) / 9 - (n0 + 8 - uv) / 9;
            tbl[10 + uv] = (r0 + 8 - uv) / 9;
            acc += cnt;
        }
        tbl[9] = acc;
    }
    __syncthreads();

    for (int e = tid; e < 8192; e += 512) {
        int m = e >> 8, rem = e & 255;
        int uv = 0;
#pragma unroll
        for (int q = 1; q < 9; q++) uv += (rem >= tbl[q]);
        int fi = rem - tbl[uv];
        int fidx = tbl[10 + uv] + fi;
        int s = s0, f = fidx;
        if (fidx >= 128) { f = fidx - 128; s = s0 + 1; }
        int r = f * 9 + uv;
        int jloc = (s - s0) * 1152 + r - r0;
        g_W2[(((size_t)m * 9 + uv) * 128 + s) * 128 + f] = sOut[m * 266 + jloc];
    }
}

// ===========================================================================
// Kernel C (v7, tf32): conv GEMM, resident fp32 x-slice + per-f-group private
// A stripe rings with named barriers (full __syncthreads only @ ast 0/8/9).
// smem: XS @0 (97920) | A stripes @97920: 4grp x 3buf x 10240 -> 220800 B
// ===========================================================================
#define XSP    272          // 68 floats
#define XSSZ   97920
#define ASP    160          // A stripe pitch bytes (40 floats)
#define ASBUF  10240        // 64 rows x 160
#define CSMEM  220800

__global__ __launch_bounds__(512, 1) void conv_mma_kernel(
    const float* __restrict__ xin,
    const float* __restrict__ bias,
    float* __restrict__ out)
{
    extern __shared__ char smem[];
    const uint32_t sb = smem_u32(smem);
    const int tid = threadIdx.x, wid = tid >> 5, lane = tid & 31;
    const int b = blockIdx.y, pb = blockIdx.x;   // pixel rows pb*8..pb*8+7
    const int grp = wid >> 2, gtid = tid & 127;
    const int f0 = grp * 32;
    const int px0 = (wid & 3) * 64;
    const int g = lane >> 2, tig = lane & 3;

    float d[2][8][4];
#pragma unroll
    for (int i = 0; i < 2; i++)
#pragma unroll
        for (int j = 0; j < 8; j++)
#pragma unroll
            for (int e = 0; e < 4; e++) d[i][j][e] = 0.0f;

    uint32_t bbase[8];
#pragma unroll
    for (int nt = 0; nt < 8; nt++) {
        int prow = (px0 >> 5) + (nt >> 2);
        int pcol = (nt & 3) * 8 + g;
        bbase[nt] = (uint32_t)((prow * 36 + pcol) * XSP + tig * 4);
    }

    const uint32_t astripe = sb + XSSZ + (uint32_t)(grp * 3) * ASBUF;

    auto load_xslice = [&](int sc) {
        for (int i = tid; i < 5760; i += 512) {
            int r = i / 576, rem = i % 576;
            int c = rem >> 4, seg = rem & 15;
            const float* src = g_xt +
                (((size_t)(b * 34 + pb * 8 + r)) * 36 + c) * 128 + sc * 64 + seg * 4;
            cp16(sb + (uint32_t)((r * 36 + c) * XSP + seg * 16), src);
        }
        CP_COMMIT();
    };

    auto issueA = [&](int ast) {
        const int uv = ast % 9, sc = ast / 9;
        const uint32_t base = astripe + (uint32_t)(ast % 3) * ASBUF;
        const float* srcb = g_W2 + ((size_t)(b * 9 + uv) * 128 + sc * 64) * 128 + f0;
#pragma unroll
        for (int i = 0; i < 4; i++) {
            int c2 = i * 128 + gtid;                 // 0..511
            int srow = c2 >> 3, seg = c2 & 7;
            cp16(base + (uint32_t)(srow * ASP + seg * 16), srcb + srow * 128 + seg * 4);
        }
        CP_COMMIT();
    };

    load_xslice(0);
    issueA(0);
    issueA(1);

    for (int ast = 0; ast < 18; ast++) {
        if (ast == 9 || ast == 17) asm volatile("cp.async.wait_group 0;" ::: "memory");
        else                       asm volatile("cp.async.wait_group 1;" ::: "memory");
        if (ast == 0 || ast == 9) __syncthreads();   // x-slice cross-group visibility
        else                      GBAR(1 + grp);     // group-local A readiness
        if (ast + 2 < 18) issueA(ast + 2);

        const int uv = ast % 9;
        const int u = uv / 3, v = uv - 3 * u;
        const uint32_t uvoff = (uint32_t)((u * 36 + v) * XSP);
        const uint32_t baseA = astripe + (uint32_t)(ast % 3) * ASBUF;
        const uint32_t abase0 = baseA + (uint32_t)(tig * ASP + g * 4);

#pragma unroll
        for (int kk = 0; kk < 8; kk++) {
            const uint32_t ab = abase0 + (uint32_t)(kk * 8 * ASP);
            uint32_t a[2][4];
#pragma unroll
            for (int mt = 0; mt < 2; mt++) {
                const uint32_t abm = ab + (uint32_t)(mt * 64);
                a[mt][0] = lds32(abm);
                a[mt][1] = lds32(abm + 32);
                a[mt][2] = lds32(abm + 4 * ASP);
                a[mt][3] = lds32(abm + 4 * ASP + 32);
            }
            const uint32_t ko = (uint32_t)kk * 32;
#pragma unroll
            for (int nt = 0; nt < 8; nt++) {
                uint32_t bfr[2];
                const uint32_t bbv = sb + bbase[nt] + uvoff + ko;
                bfr[0] = lds32(bbv);
                bfr[1] = lds32(bbv + 16);
#pragma unroll
                for (int mt = 0; mt < 2; mt++)
                    mma1688_tf32(d[mt][nt], a[mt], bfr);
            }
        }

        if (ast == 8) {            // slice 0 fully consumed by ALL groups
            __syncthreads();
            load_xslice(1);
        }
    }

    // ---- epilogue: + residual + bias ----
    const int tc = lane & 3;
#pragma unroll
    for (int i = 0; i < 2; i++) {
        const int fr0 = f0 + i * 16 + g;
        const float bv0 = __ldg(&bias[fr0]);
        const float bv1 = __ldg(&bias[fr0 + 8]);
#pragma unroll
        for (int j = 0; j < 8; j++) {
            const int pix = pb * 256 + px0 + j * 8 + tc * 2;
            {
                size_t o = ((size_t)(b * 128 + fr0)) * 1024 + pix;
                float2 xr = *reinterpret_cast<const float2*>(xin + o);
                float2 w = make_float2(d[i][j][0] + xr.x + bv0,
                                       d[i][j][1] + xr.y + bv0);
                *reinterpret_cast<float2*>(out + o) = w;
            }
            {
                size_t o = ((size_t)(b * 128 + fr0 + 8)) * 1024 + pix;
                float2 xr = *reinterpret_cast<const float2*>(xin + o);
                float2 w = make_float2(d[i][j][2] + xr.x + bv1,
                                       d[i][j][3] + xr.y + bv1);
                *reinterpret_cast<float2*>(out + o) = w;
            }
        }
    }
}

// ===========================================================================
extern "C" void kernel_launch(void* const* d_in, const int* in_sizes, int n_in,
                              void* d_out, int out_size)
{
    (void)in_sizes; (void)n_in; (void)out_size;
    const float* x     = (const float*)d_in[0];
    const float* z     = (const float*)d_in[1];
    const float* dw    = (const float*)d_in[2];
    const float* db    = (const float*)d_in[3];
    const float* gamma = (const float*)d_in[4];
    const float* beta  = (const float*)d_in[5];
    const float* bconv = (const float*)d_in[6];
    float* out = (float*)d_out;

    cudaFuncSetAttribute(hyper_tf32_kernel,
                         cudaFuncAttributeMaxDynamicSharedMemorySize, H2_SMEM);
    cudaFuncSetAttribute(conv_mma_kernel,
                         cudaFuncAttributeMaxDynamicSharedMemorySize, CSMEM);

    hyper_tf32_kernel<<<NB / 256, 512, H2_SMEM>>>(z, dw, db, gamma, beta, x);
    conv_mma_kernel<<<dim3(4, BATCH), 512, CSMEM>>>(x, bconv, out);
}

// round 16
// speedup vs baseline: 1.1197x; 1.0087x over previous
#include <cuda_runtime.h>
#include <cuda_bf16.h>
#include <cstdint>

#define CIN   128
#define COUT  128
#define KHW   9
#define NB    (CIN*COUT*KHW)   // 147456
#define ZD    256
#define BATCH 32
#define HW    32
#define HW2   (HW*HW)

// ---------------- scratch (device globals; no allocs allowed) ----------------
__device__ __align__(1024) float g_W2[BATCH * 9 * 128 * 128];      // tf32-rounded (b, uv, s, f)
__device__ __align__(1024) float g_xt[BATCH * 34 * 36 * 128];      // tf32-rounded (b,row,col,s); pad stays 0

// ---------------- helpers ----------------
__device__ __forceinline__ uint32_t smem_u32(const void* p) {
    uint32_t a;
    asm("{ .reg .u64 t; cvta.to.shared.u64 t, %1; cvt.u32.u64 %0, t; }" : "=r"(a) : "l"(p));
    return a;
}
__device__ __forceinline__ void cp16(uint32_t dst, const void* src) {
    asm volatile("cp.async.cg.shared.global [%0], [%1], 16;" :: "r"(dst), "l"(src) : "memory");
}
#define CP_COMMIT() asm volatile("cp.async.commit_group;" ::: "memory")

__device__ __forceinline__ void mma1688_tf32(float* d, const uint32_t* a, const uint32_t* b) {
    asm volatile(
        "mma.sync.aligned.m16n8k8.row.col.f32.tf32.tf32.f32 "
        "{%0,%1,%2,%3}, {%4,%5,%6,%7}, {%8,%9}, {%0,%1,%2,%3};"
        : "+f"(d[0]), "+f"(d[1]), "+f"(d[2]), "+f"(d[3])
        : "r"(a[0]), "r"(a[1]), "r"(a[2]), "r"(a[3]), "r"(b[0]), "r"(b[1]));
}
__device__ __forceinline__ uint32_t cvt_tf32(float f) {
    uint32_t r;
    asm("cvt.rna.tf32.f32 %0, %1;" : "=r"(r) : "f"(f));
    return r;
}
__device__ __forceinline__ uint32_t lds32(uint32_t a) {
    uint32_t r;
    asm volatile("ld.shared.b32 %0, [%1];" : "=r"(r) : "r"(a));
    return r;
}
#define GBAR(id) asm volatile("bar.sync %0, %1;" :: "r"(id), "r"(128) : "memory")

// ===========================================================================
// Kernel A (tf32, warp-private B stripes, NO mainloop barriers) + embedded
// x-prep in the prologue. (proven R15)
// ===========================================================================
#define H2_APW 268
#define H2_RB  34304
#define H2_SMEM 108032

__global__ __launch_bounds__(512, 2) void hyper_tf32_kernel(
    const float* __restrict__ z, const float* __restrict__ dw,
    const float* __restrict__ db, const float* __restrict__ gamma,
    const float* __restrict__ beta, const float* __restrict__ x)
{
    extern __shared__ char hs[];
    const uint32_t sb = smem_u32(hs);
    const int tid = threadIdx.x, wid = tid >> 5, lane = tid & 31;
    const int n0 = blockIdx.x * 256;
    const int wn0 = wid * 16;
    const int g = lane >> 2, tig = lane & 3;

    const uint32_t bstripe = sb + H2_RB + (uint32_t)(wid * 3) * 1536;

    auto issue = [&](int s) {
        const uint32_t base = bstripe + (uint32_t)(s % 3) * 1536;
#pragma unroll
        for (int i = 0; i < 2; i++) {
            int chunk = i * 32 + lane;
            int row = chunk >> 2, seg = chunk & 3;
            cp16(base + (uint32_t)(row * 96 + seg * 16),
                 dw + (size_t)(s * 16 + row) * NB + n0 + wn0 + seg * 4);
        }
        CP_COMMIT();
    };
    issue(0);
    issue(1);
    issue(2);

    // ---- embedded x-prep: ~2 (b,p) columns per CTA, staged in A region ----
    {
        float* sX = reinterpret_cast<float*>(hs);
        const int p0 = (blockIdx.x * 1024) / 576;
        const int p1 = ((blockIdx.x + 1) * 1024) / 576;
        for (int pr = p0; pr < p1; pr++) {
            const int xb = pr >> 5, xp = pr & 31;
            const int row = tid >> 2, qs = (tid & 3) * 8;
            const float* src = x + ((size_t)(xb * 128 + row) * 32 + xp) * 32 + qs;
            float4 v0 = *reinterpret_cast<const float4*>(src);
            float4 v1 = *reinterpret_cast<const float4*>(src + 4);
            float* dr = &sX[row * 33 + qs];
            dr[0] = v0.x; dr[1] = v0.y; dr[2] = v0.z; dr[3] = v0.w;
            dr[4] = v1.x; dr[5] = v1.y; dr[6] = v1.z; dr[7] = v1.w;
            __syncthreads();
            const int idx = tid * 8, q = idx >> 7, s0 = idx & 127;
            float o8[8];
#pragma unroll
            for (int i = 0; i < 8; i++)
                o8[i] = __uint_as_float(cvt_tf32(sX[(s0 + i) * 33 + q]));
            float* dst = g_xt + (((size_t)xb * 34 + xp + 1) * 36 + (q + 1)) * 128 + s0;
            *reinterpret_cast<float4*>(dst)     = make_float4(o8[0], o8[1], o8[2], o8[3]);
            *reinterpret_cast<float4*>(dst + 4) = make_float4(o8[4], o8[5], o8[6], o8[7]);
            __syncthreads();
        }
    }

    // A (z) -> tf32 (rna) smem [m=32][k=256]
    {
        const int m = tid >> 4, k0 = (tid & 15) * 16;
        const float4* zsrc = reinterpret_cast<const float4*>(z + m * ZD + k0);
        uint32_t* arow = reinterpret_cast<uint32_t*>(hs) + m * H2_APW + k0;
#pragma unroll
        for (int j = 0; j < 4; j++) {
            float4 v = zsrc[j];
            arow[j * 4 + 0] = cvt_tf32(v.x);
            arow[j * 4 + 1] = cvt_tf32(v.y);
            arow[j * 4 + 2] = cvt_tf32(v.z);
            arow[j * 4 + 3] = cvt_tf32(v.w);
        }
    }
    __syncthreads();

    float d[2][2][4];
#pragma unroll
    for (int mt = 0; mt < 2; mt++)
#pragma unroll
        for (int nt = 0; nt < 2; nt++)
#pragma unroll
            for (int e = 0; e < 4; e++) d[mt][nt][e] = 0.0f;

    const uint32_t abase = sb + (uint32_t)(g * H2_APW + tig) * 4;

    for (int s = 0; s < 16; s++) {
        if (s < 14)      asm volatile("cp.async.wait_group 2;" ::: "memory");
        else if (s == 14) asm volatile("cp.async.wait_group 1;" ::: "memory");
        else              asm volatile("cp.async.wait_group 0;" ::: "memory");

        const uint32_t bbuf = bstripe + (uint32_t)(s % 3) * 1536;
#pragma unroll
        for (int kk = 0; kk < 2; kk++) {
            const uint32_t acol = (uint32_t)(s * 16 + kk * 8) * 4;
            uint32_t a[2][4], bfr[2][2];
#pragma unroll
            for (int mt = 0; mt < 2; mt++) {
                const uint32_t ab = abase + (uint32_t)(mt * 16 * H2_APW) * 4 + acol;
                a[mt][0] = lds32(ab);
                a[mt][1] = lds32(ab + (uint32_t)(8 * H2_APW) * 4);
                a[mt][2] = lds32(ab + 16);
                a[mt][3] = lds32(ab + (uint32_t)(8 * H2_APW) * 4 + 16);
            }
#pragma unroll
            for (int nt = 0; nt < 2; nt++) {
                const uint32_t bb = bbuf + (uint32_t)(((kk * 8 + tig) * 24 + nt * 8 + g)) * 4;
                bfr[nt][0] = cvt_tf32(__uint_as_float(lds32(bb)));
                bfr[nt][1] = cvt_tf32(__uint_as_float(lds32(bb + 4 * 24 * 4)));
            }
#pragma unroll
            for (int mt = 0; mt < 2; mt++)
#pragma unroll
                for (int nt = 0; nt < 2; nt++)
                    mma1688_tf32(d[mt][nt], a[mt], bfr[nt]);
        }
        if (s + 3 < 16) issue(s + 3);
    }

    // ---- epilogue: relu + BN ----
    const int jc = n0 + wn0 + 2 * tig;
    float2 db2[2], g2[2], bt2[2];
#pragma unroll
    for (int nt = 0; nt < 2; nt++) {
        db2[nt] = *reinterpret_cast<const float2*>(db + jc + nt * 8);
        g2[nt]  = *reinterpret_cast<const float2*>(gamma + jc + nt * 8);
        bt2[nt] = *reinterpret_cast<const float2*>(beta + jc + nt * 8);
    }
#pragma unroll
    for (int mt = 0; mt < 2; mt++)
#pragma unroll
        for (int nt = 0; nt < 2; nt++) {
            d[mt][nt][0] = fmaxf(d[mt][nt][0] + db2[nt].x, 0.0f);
            d[mt][nt][1] = fmaxf(d[mt][nt][1] + db2[nt].y, 0.0f);
            d[mt][nt][2] = fmaxf(d[mt][nt][2] + db2[nt].x, 0.0f);
            d[mt][nt][3] = fmaxf(d[mt][nt][3] + db2[nt].y, 0.0f);
        }

    float sm[2][2], sq[2][2];
#pragma unroll
    for (int nt = 0; nt < 2; nt++)
#pragma unroll
        for (int c = 0; c < 2; c++) {
            float s1 = d[0][nt][c] + d[0][nt][c + 2] + d[1][nt][c] + d[1][nt][c + 2];
            float q1 = d[0][nt][c] * d[0][nt][c] + d[0][nt][c + 2] * d[0][nt][c + 2]
                     + d[1][nt][c] * d[1][nt][c] + d[1][nt][c + 2] * d[1][nt][c + 2];
#pragma unroll
            for (int o = 4; o < 32; o <<= 1) {
                s1 += __shfl_xor_sync(0xffffffffu, s1, o);
                q1 += __shfl_xor_sync(0xffffffffu, q1, o);
            }
            sm[nt][c] = s1 * (1.0f / 32.0f);
            float var = fmaxf(q1 * (1.0f / 32.0f) - sm[nt][c] * sm[nt][c], 0.0f);
            float gm = (c == 0) ? ((nt == 0) ? g2[0].x : g2[1].x)
                                : ((nt == 0) ? g2[0].y : g2[1].y);
            sq[nt][c] = gm / (sqrtf(var) + 1e-6f);
        }

    __syncthreads();

    float* sOut = reinterpret_cast<float*>(hs + H2_RB);
    const int jl0 = wn0 + 2 * tig;
#pragma unroll
    for (int mt = 0; mt < 2; mt++)
#pragma unroll
        for (int nt = 0; nt < 2; nt++) {
            const int jl = jl0 + nt * 8;
            float2 o0 = make_float2((d[mt][nt][0] - sm[nt][0]) * sq[nt][0] + bt2[nt].x,
                                    (d[mt][nt][1] - sm[nt][1]) * sq[nt][1] + bt2[nt].y);
            float2 o1 = make_float2((d[mt][nt][2] - sm[nt][0]) * sq[nt][0] + bt2[nt].x,
                                    (d[mt][nt][3] - sm[nt][1]) * sq[nt][1] + bt2[nt].y);
            *reinterpret_cast<float2*>(&sOut[(mt * 16 + g) * 266 + jl]) = o0;
            *reinterpret_cast<float2*>(&sOut[(mt * 16 + g + 8) * 266 + jl]) = o1;
        }

    int* tbl = reinterpret_cast<int*>(hs + H2_RB + 40960);
    const int r0 = n0 % 1152, s0 = n0 / 1152;
    if (tid == 0) {
        int acc = 0;
        for (int uv = 0; uv < 9; uv++) {
            tbl[uv] = acc;
            int cnt = (n0 + 264 - uv) / 9 - (n0 + 8 - uv) / 9;
            tbl[10 + uv] = (r0 + 8 - uv) / 9;
            acc += cnt;
        }
        tbl[9] = acc;
    }
    __syncthreads();

    for (int e = tid; e < 8192; e += 512) {
        int m = e >> 8, rem = e & 255;
        int uv = 0;
#pragma unroll
        for (int q = 1; q < 9; q++) uv += (rem >= tbl[q]);
        int fi = rem - tbl[uv];
        int fidx = tbl[10 + uv] + fi;
        int s = s0, f = fidx;
        if (fidx >= 128) { f = fidx - 128; s = s0 + 1; }
        int r = f * 9 + uv;
        int jloc = (s - s0) * 1152 + r - r0;
        g_W2[(((size_t)m * 9 + uv) * 128 + s) * 128 + f] = sOut[m * 266 + jloc];
    }
}

// ===========================================================================
// Kernel C (v8, tf32): 256 thr, 8 warps, warp tile 64f x 64px.
//   CTA tile 128f x 256px (grid 128). Per-f-half A stripe rings [64k][64f]
//   pitch 72 fl; named barrier per f-half; full syncs only @ ast 0/8/9.
//   LDS/MMA ratio 1.0 (vs 1.5) -> crossbar floor balanced with tensor floor.
// smem: XS @0 (97920) | A stripes @97920: 2grp x 3buf x 18432 -> 208512 B
// ===========================================================================
#define XSP    272          // 68 floats
#define XSSZ   97920
#define ASP    288          // A stripe pitch bytes (72 floats; 72%32==8)
#define ASBUF  18432        // 64 rows x 288
#define CSMEM  208512

__global__ __launch_bounds__(256, 1) void conv_mma_kernel(
    const float* __restrict__ xin,
    const float* __restrict__ bias,
    float* __restrict__ out)
{
    extern __shared__ char smem[];
    const uint32_t sb = smem_u32(smem);
    const int tid = threadIdx.x, wid = tid >> 5, lane = tid & 31;
    const int b = blockIdx.y, pb = blockIdx.x;   // pixel rows pb*8..pb*8+7
    const int fh = wid >> 2, gtid = tid & 127;   // f-half group
    const int f0 = fh * 64;
    const int px0 = (wid & 3) * 64;
    const int g = lane >> 2, tig = lane & 3;

    float d[4][8][4];
#pragma unroll
    for (int i = 0; i < 4; i++)
#pragma unroll
        for (int j = 0; j < 8; j++)
#pragma unroll
            for (int e = 0; e < 4; e++) d[i][j][e] = 0.0f;

    uint32_t bbase[8];
#pragma unroll
    for (int nt = 0; nt < 8; nt++) {
        int prow = (px0 >> 5) + (nt >> 2);
        int pcol = (nt & 3) * 8 + g;
        bbase[nt] = (uint32_t)((prow * 36 + pcol) * XSP + tig * 4);
    }

    const uint32_t astripe = sb + XSSZ + (uint32_t)(fh * 3) * ASBUF;

    auto load_xslice = [&](int sc) {
        for (int i = tid; i < 5760; i += 256) {
            int r = i / 576, rem = i % 576;
            int c = rem >> 4, seg = rem & 15;
            const float* src = g_xt +
                (((size_t)(b * 34 + pb * 8 + r)) * 36 + c) * 128 + sc * 64 + seg * 4;
            cp16(sb + (uint32_t)((r * 36 + c) * XSP + seg * 16), src);
        }
        CP_COMMIT();
    };

    auto issueA = [&](int ast) {
        const int uv = ast % 9, sc = ast / 9;
        const uint32_t base = astripe + (uint32_t)(ast % 3) * ASBUF;
        const float* srcb = g_W2 + ((size_t)(b * 9 + uv) * 128 + sc * 64) * 128 + f0;
#pragma unroll
        for (int i = 0; i < 8; i++) {
            int c2 = i * 128 + gtid;                 // 0..1023
            int srow = c2 >> 4, seg = c2 & 15;
            cp16(base + (uint32_t)(srow * ASP + seg * 16), srcb + srow * 128 + seg * 4);
        }
        CP_COMMIT();
    };

    load_xslice(0);
    issueA(0);
    issueA(1);

    for (int ast = 0; ast < 18; ast++) {
        if (ast == 9 || ast == 17) asm volatile("cp.async.wait_group 0;" ::: "memory");
        else                       asm volatile("cp.async.wait_group 1;" ::: "memory");
        if (ast == 0 || ast == 9) __syncthreads();   // x-slice cross-group visibility
        else                      GBAR(1 + fh);      // group-local A readiness
        if (ast + 2 < 18) issueA(ast + 2);

        const int uv = ast % 9;
        const int u = uv / 3, v = uv - 3 * u;
        const uint32_t uvoff = (uint32_t)((u * 36 + v) * XSP);
        const uint32_t baseA = astripe + (uint32_t)(ast % 3) * ASBUF;
        const uint32_t abase0 = baseA + (uint32_t)(tig * ASP + g * 4);

#pragma unroll
        for (int kk = 0; kk < 8; kk++) {
            const uint32_t ab = abase0 + (uint32_t)(kk * 8 * ASP);
            uint32_t a[4][4];
#pragma unroll
            for (int mt = 0; mt < 4; mt++) {
                const uint32_t abm = ab + (uint32_t)(mt * 64);
                a[mt][0] = lds32(abm);
                a[mt][1] = lds32(abm + 32);
                a[mt][2] = lds32(abm + 4 * ASP);
                a[mt][3] = lds32(abm + 4 * ASP + 32);
            }
            const uint32_t ko = (uint32_t)kk * 32;
#pragma unroll
            for (int nt = 0; nt < 8; nt++) {
                uint32_t bfr[2];
                const uint32_t bbv = sb + bbase[nt] + uvoff + ko;
                bfr[0] = lds32(bbv);
                bfr[1] = lds32(bbv + 16);
#pragma unroll
                for (int mt = 0; mt < 4; mt++)
                    mma1688_tf32(d[mt][nt], a[mt], bfr);
            }
        }

        if (ast == 8) {            // slice 0 fully consumed by ALL groups
            __syncthreads();
            load_xslice(1);
        }
    }

    // ---- epilogue: + residual + bias ----
    const int tc = lane & 3;
#pragma unroll
    for (int mt = 0; mt < 4; mt++) {
        const int fr0 = f0 + mt * 16 + g;
        const float bv0 = __ldg(&bias[fr0]);
        const float bv1 = __ldg(&bias[fr0 + 8]);
#pragma unroll
        for (int j = 0; j < 8; j++) {
            const int pix = pb * 256 + px0 + j * 8 + tc * 2;
            {
                size_t o = ((size_t)(b * 128 + fr0)) * 1024 + pix;
                float2 xr = *reinterpret_cast<const float2*>(xin + o);
                float2 w = make_float2(d[mt][j][0] + xr.x + bv0,
                                       d[mt][j][1] + xr.y + bv0);
                *reinterpret_cast<float2*>(out + o) = w;
            }
            {
                size_t o = ((size_t)(b * 128 + fr0 + 8)) * 1024 + pix;
                float2 xr = *reinterpret_cast<const float2*>(xin + o);
                float2 w = make_float2(d[mt][j][2] + xr.x + bv1,
                                       d[mt][j][3] + xr.y + bv1);
                *reinterpret_cast<float2*>(out + o) = w;
            }
        }
    }
}

// ===========================================================================
extern "C" void kernel_launch(void* const* d_in, const int* in_sizes, int n_in,
                              void* d_out, int out_size)
{
    (void)in_sizes; (void)n_in; (void)out_size;
    const float* x     = (const float*)d_in[0];
    const float* z     = (const float*)d_in[1];
    const float* dw    = (const float*)d_in[2];
    const float* db    = (const float*)d_in[3];
    const float* gamma = (const float*)d_in[4];
    const float* beta  = (const float*)d_in[5];
    const float* bconv = (const float*)d_in[6];
    float* out = (float*)d_out;

    cudaFuncSetAttribute(hyper_tf32_kernel,
                         cudaFuncAttributeMaxDynamicSharedMemorySize, H2_SMEM);
    cudaFuncSetAttribute(conv_mma_kernel,
                         cudaFuncAttributeMaxDynamicSharedMemorySize, CSMEM);

    hyper_tf32_kernel<<<NB / 256, 512, H2_SMEM>>>(z, dw, db, gamma, beta, x);
    conv_mma_kernel<<<dim3(4, BATCH), 256, CSMEM>>>(x, bconv, out);
}